// round 16
// baseline (speedup 1.0000x reference)
#include <cuda_runtime.h>
#include <cuda_bf16.h>
#include <math.h>

#define Bb 4
#define Nn 1024
#define Ee 256
#define Hh 8
#define Dd 32

// ---------------- scratch (device globals; referenced ONLY inside kernels) ----
__device__ float g_Wh[(size_t)Hh*Bb*Nn*Dd];        // [h][b][n][d]  4MB
__device__ float g_s1[Hh*Bb*Nn];
__device__ float g_s2[Hh*Bb*Nn];
__device__ float g_rmx[Hh*Bb*Nn];                  // GAT softmax row max
__device__ float g_rsm[Hh*Bb*Nn];                  // GAT softmax row sum
__device__ unsigned g_adjbits[Bb*Nn*32];           // packed adjacency
__device__ float g_x1[Bb*Nn*Ee];                   // GAT residual output
__device__ float g_tA[Bb*Nn*Ee];
__device__ float g_tB[Bb*Nn*Ee];
__device__ float g_q[Bb*Nn*Ee];
__device__ float g_k[Bb*Nn*Ee];
__device__ float g_v[Bb*Nn*Ee];
__device__ float g_o[Bb*Nn*Ee];
__device__ float g_eout[(size_t)Bb*Nn*Nn];         // e_out staging (only if unused output)
__device__ float g_xout[Bb*Nn*Ee];                 // x staging
__device__ float g_psum[512*Ee];                   // per-rownorm-block col partials
__device__ float g_psq [512*Ee];
__device__ float g_cmean[Bb*Ee];
__device__ float g_crstd[Bb*Ee];

// ---------------- helpers ----------------
__device__ __forceinline__ void ffma2(unsigned long long& acc,
                                      unsigned long long a, unsigned long long b) {
    asm("fma.rn.f32x2 %0, %1, %2, %0;" : "+l"(acc) : "l"(a), "l"(b));
}
__device__ __forceinline__ void fmul2(unsigned long long& acc, unsigned long long s) {
    asm("mul.rn.f32x2 %0, %0, %1;" : "+l"(acc) : "l"(s));
}
__device__ __forceinline__ unsigned long long dup2(float x) {
    unsigned long long r;
    asm("mov.b64 %0, {%1, %1};" : "=l"(r) : "f"(x));
    return r;
}
__device__ __forceinline__ float f2lo(unsigned long long p) {
    return __uint_as_float((unsigned)(p & 0xffffffffu));
}
__device__ __forceinline__ float f2hi(unsigned long long p) {
    return __uint_as_float((unsigned)(p >> 32));
}
__device__ __forceinline__ float f2sum(unsigned long long p) { return f2lo(p) + f2hi(p); }

// ---------------- K0: pack adjacency into bitmasks ----------------
__global__ void k_adjpack(const int* __restrict__ adj) {
    int row = blockIdx.x;                 // b*N + n
    int w = threadIdx.x >> 5, lane = threadIdx.x & 31;
    #pragma unroll
    for (int i = 0; i < 4; i++) {
        int u = w * 4 + i;
        unsigned bit = adj[(size_t)row * Nn + u * 32 + lane] > 0 ? 1u : 0u;
        unsigned mask = __ballot_sync(0xffffffffu, bit);
        if (lane == 0) g_adjbits[row * 32 + u] = mask;
    }
}

// ---------------- K1: Wh = x @ Wg per head, GEMM-tiled, s1/s2 fused ------------
__global__ void k_wh2(const float* __restrict__ x, const float* __restrict__ Wg,
                      const float* __restrict__ a1, const float* __restrict__ a2) {
    __shared__ float As[128 * 66];   // [row][f-chunk]  33.8KB
    __shared__ float Ws[32 * 66];    // [d][f-chunk]    8.4KB (Wg transposed)
    int tile = blockIdx.x, h = blockIdx.y;
    int t = threadIdx.x;
    int tr = t >> 4, ti = t & 15;
    int bn0 = tile * 128;
    int b = bn0 >> 10;
    int hb = h * Bb + b;

    unsigned long long acc2[8][2];
    #pragma unroll
    for (int r = 0; r < 8; r++) { acc2[r][0] = 0ull; acc2[r][1] = 0ull; }

    for (int kt = 0; kt < 256; kt += 64) {
        #pragma unroll
        for (int i = 0; i < 32; i++) {
            int idx = i * 256 + t;
            int r = idx >> 6, k = idx & 63;
            As[r * 66 + k] = x[(size_t)(bn0 + r) * 256 + kt + k];
        }
        #pragma unroll
        for (int i = 0; i < 8; i++) {
            int idx = i * 256 + t;
            int d = idx >> 6, k = idx & 63;
            Ws[d * 66 + k] = Wg[h * 8192 + (kt + k) * 32 + d];
        }
        __syncthreads();
        #pragma unroll
        for (int k2 = 0; k2 < 32; k2++) {
            unsigned long long a2[8], w2[2];
            #pragma unroll
            for (int r = 0; r < 8; r++)
                a2[r] = *(const unsigned long long*)&As[(tr + r * 16) * 66 + 2 * k2];
            w2[0] = *(const unsigned long long*)&Ws[(ti * 2 + 0) * 66 + 2 * k2];
            w2[1] = *(const unsigned long long*)&Ws[(ti * 2 + 1) * 66 + 2 * k2];
            #pragma unroll
            for (int r = 0; r < 8; r++) {
                ffma2(acc2[r][0], a2[r], w2[0]);
                ffma2(acc2[r][1], a2[r], w2[1]);
            }
        }
        __syncthreads();
    }

    float a1v0 = a1[h * 32 + ti * 2], a1v1 = a1[h * 32 + ti * 2 + 1];
    float a2v0 = a2[h * 32 + ti * 2], a2v1 = a2[h * 32 + ti * 2 + 1];
    #pragma unroll
    for (int r = 0; r < 8; r++) {
        int bn = bn0 + tr + r * 16;
        int n = bn & 1023;
        float v0 = f2sum(acc2[r][0]), v1 = f2sum(acc2[r][1]);
        *(float2*)&g_Wh[((size_t)hb * Nn + n) * 32 + ti * 2] = make_float2(v0, v1);
        float s1p = v0 * a1v0 + v1 * a1v1;
        float s2p = v0 * a2v0 + v1 * a2v1;
        #pragma unroll
        for (int o = 8; o > 0; o >>= 1) {
            s1p += __shfl_xor_sync(0xffffffffu, s1p, o);
            s2p += __shfl_xor_sync(0xffffffffu, s2p, o);
        }
        if (ti == 0) {
            g_s1[hb * Nn + n] = s1p;
            g_s2[hb * Nn + n] = s2p;
        }
    }
}

// ---------------- K2: GAT flash (128 threads, 4 rows/thread) -------------------
__global__ void __launch_bounds__(128, 4) k_gat_flash(const float* __restrict__ x) {
    __shared__ float Ws[32 * 66];    // [d][m]
    __shared__ float Ps[64 * 66];    // [row][m]
    __shared__ float s2s[64];
    __shared__ unsigned adjw[64 * 2];
    int tile = blockIdx.x, b = blockIdx.y, h = blockIdx.z;
    int t = threadIdx.x, tr = t >> 3, ti = t & 7;
    int n0 = tile * 64;
    int hb = h * Bb + b;
    const float* whp = g_Wh + (size_t)hb * Nn * 32;

    float s1r[4];
    #pragma unroll
    for (int r = 0; r < 4; r++) s1r[r] = g_s1[hb * Nn + n0 + tr * 4 + r];

    float m_run[4], l_run[4];
    unsigned long long acc2[4][4];
    #pragma unroll
    for (int r = 0; r < 4; r++) {
        m_run[r] = -1e30f; l_run[r] = 0.f;
        #pragma unroll
        for (int j = 0; j < 4; j++) acc2[r][j] = 0ull;
    }

    int ubase = ti >> 2;
    int bshift = (ti & 3) * 8;

    for (int ch = 0; ch < 16; ch++) {
        int m0 = ch * 64;
        #pragma unroll
        for (int i = 0; i < 16; i++) {
            int idx = i * 128 + t;
            int m = idx >> 5, d = idx & 31;
            Ws[d * 66 + m] = whp[(m0 + m) * 32 + d];
        }
        if (t < 64) s2s[t] = g_s2[hb * Nn + m0 + t];
        { int rl = t >> 1, u = t & 1;
          adjw[rl * 2 + u] = g_adjbits[(size_t)(b * Nn + n0 + rl) * 32 + (m0 >> 5) + u]; }
        __syncthreads();

        float s2v[8];
        #pragma unroll
        for (int c = 0; c < 8; c++) s2v[c] = s2s[ti * 8 + c];
        unsigned aw[4];
        #pragma unroll
        for (int r = 0; r < 4; r++) aw[r] = adjw[(tr * 4 + r) * 2 + ubase];

        float cmax[4];
        #pragma unroll
        for (int r = 0; r < 4; r++) {
            float cm = -1e30f;
            #pragma unroll
            for (int c = 0; c < 8; c++) {
                float e = s1r[r] + s2v[c];
                e = e >= 0.f ? e : 0.1f * e;
                if (!((aw[r] >> (bshift + c)) & 1u)) e = -9e15f;
                cm = fmaxf(cm, e);
            }
            #pragma unroll
            for (int o = 1; o < 8; o <<= 1) cm = fmaxf(cm, __shfl_xor_sync(0xffffffffu, cm, o));
            cmax[r] = cm;
        }
        #pragma unroll
        for (int r = 0; r < 4; r++) {
            float m_new = fmaxf(m_run[r], cmax[r]);
            float sc = __expf(m_run[r] - m_new);
            m_run[r] = m_new;
            unsigned long long sc2 = dup2(sc);
            #pragma unroll
            for (int j = 0; j < 4; j++) fmul2(acc2[r][j], sc2);
            float rs = 0.f;
            #pragma unroll
            for (int c = 0; c < 8; c++) {
                float e = s1r[r] + s2v[c];
                e = e >= 0.f ? e : 0.1f * e;
                if (!((aw[r] >> (bshift + c)) & 1u)) e = -9e15f;
                float p = __expf(e - m_new);
                Ps[(tr * 4 + r) * 66 + ti * 8 + c] = p;
                rs += p;
            }
            #pragma unroll
            for (int o = 1; o < 8; o <<= 1) rs += __shfl_xor_sync(0xffffffffu, rs, o);
            l_run[r] = l_run[r] * sc + rs;
        }
        __syncthreads();
        #pragma unroll
        for (int k2 = 0; k2 < 32; k2++) {
            unsigned long long a2[4], w2[4];
            #pragma unroll
            for (int r = 0; r < 4; r++)
                a2[r] = *(const unsigned long long*)&Ps[(tr * 4 + r) * 66 + 2 * k2];
            #pragma unroll
            for (int j = 0; j < 4; j++)
                w2[j] = *(const unsigned long long*)&Ws[(ti * 4 + j) * 66 + 2 * k2];
            #pragma unroll
            for (int r = 0; r < 4; r++)
                #pragma unroll
                for (int j = 0; j < 4; j++)
                    ffma2(acc2[r][j], a2[r], w2[j]);
        }
        __syncthreads();
    }

    #pragma unroll
    for (int r = 0; r < 4; r++) {
        int n = n0 + tr * 4 + r;
        float inv = 1.0f / l_run[r];
        if (ti == 0) {
            g_rmx[hb * Nn + n] = m_run[r];
            g_rsm[hb * Nn + n] = l_run[r];
        }
        #pragma unroll
        for (int j = 0; j < 4; j++) {
            float v = f2sum(acc2[r][j]) * inv;
            v = v >= 0.f ? v : 0.01f * v;
            int idx = (b * Nn + n) * 256 + h * 32 + ti * 4 + j;
            g_x1[idx] = x[idx] + v;
        }
    }
}

// ---------------- K3: e_out recompute from stats ----------------
__global__ void k_eout2(float* __restrict__ out) {
    __shared__ float s2all[8 * 1024];
    __shared__ unsigned adjw[32];
    __shared__ float mxs[8], invs[8], s1s[8];
    int n = blockIdx.x & 1023;
    int b = blockIdx.x >> 10;
    int t = threadIdx.x;
    #pragma unroll
    for (int i = 0; i < 32; i++) {
        int idx = i * 256 + t;
        s2all[idx] = g_s2[((idx >> 10) * Bb + b) * Nn + (idx & 1023)];
    }
    if (t < 32) adjw[t] = g_adjbits[(size_t)(b * Nn + n) * 32 + t];
    if (t < 8) {
        int hb = t * Bb + b;
        mxs[t]  = g_rmx[hb * Nn + n];
        invs[t] = 1.0f / g_rsm[hb * Nn + n];
        s1s[t]  = g_s1[hb * Nn + n];
    }
    __syncthreads();
    float* dst = out ? out : g_eout;
    #pragma unroll
    for (int i = 0; i < 4; i++) {
        int m = t + i * 256;
        unsigned bit = (adjw[m >> 5] >> (m & 31)) & 1u;
        float acc = 0.f;
        #pragma unroll
        for (int h = 0; h < 8; h++) {
            float e = s1s[h] + s2all[h * 1024 + m];
            e = e >= 0.f ? e : 0.1f * e;
            if (!bit) e = -9e15f;
            acc += __expf(e - mxs[h]) * invs[h];
        }
        dst[((size_t)b * Nn + n) * Nn + m] = acc * 0.125f;
    }
}

// ---------------- K5: row norm warp-per-row + fused col partials ---------------
// grid 512, block 256 (8 warps = 8 rows). sel=0: g_x1 -> g_tA ; 1: g_tB -> g_tA
// Also emits per-block column partial sums/sumsqs into g_psum/g_psq[block].
__global__ void k_rownorm(int sel) {
    __shared__ float vs[8 * 264];   // 8 rows x 256 (+pad)
    const float* in = sel ? g_tB : g_x1;
    int w = threadIdx.x >> 5, lane = threadIdx.x & 31;
    int bn = blockIdx.x * 8 + w;
    const float* p = in + (size_t)bn * 256 + lane * 8;
    float4 v0 = *(const float4*)p;
    float4 v1 = *(const float4*)(p + 4);
    float s = v0.x + v0.y + v0.z + v0.w + v1.x + v1.y + v1.z + v1.w;
    #pragma unroll
    for (int o = 16; o > 0; o >>= 1) s += __shfl_xor_sync(0xffffffffu, s, o);
    float mean = s * (1.0f / 256.0f);
    float d0 = v0.x-mean, d1 = v0.y-mean, d2 = v0.z-mean, d3 = v0.w-mean;
    float d4 = v1.x-mean, d5 = v1.y-mean, d6 = v1.z-mean, d7 = v1.w-mean;
    float q = d0*d0+d1*d1+d2*d2+d3*d3+d4*d4+d5*d5+d6*d6+d7*d7;
    #pragma unroll
    for (int o = 16; o > 0; o >>= 1) q += __shfl_xor_sync(0xffffffffu, q, o);
    float inv = 1.0f / (sqrtf(q * (1.0f / 255.0f)) + 1e-6f);
    float r0 = d0*inv, r1 = d1*inv, r2 = d2*inv, r3 = d3*inv;
    float r4 = d4*inv, r5 = d5*inv, r6 = d6*inv, r7 = d7*inv;
    float* op = g_tA + (size_t)bn * 256 + lane * 8;
    *(float4*)op       = make_float4(r0, r1, r2, r3);
    *(float4*)(op + 4) = make_float4(r4, r5, r6, r7);
    int cb = w * 264 + lane * 8;
    vs[cb+0]=r0; vs[cb+1]=r1; vs[cb+2]=r2; vs[cb+3]=r3;
    vs[cb+4]=r4; vs[cb+5]=r5; vs[cb+6]=r6; vs[cb+7]=r7;
    __syncthreads();
    // column partials over this block's 8 rows
    int e = threadIdx.x;
    float cs = 0.f, cq = 0.f;
    #pragma unroll
    for (int r = 0; r < 8; r++) {
        float v = vs[r * 264 + e];
        cs += v; cq += v * v;
    }
    g_psum[blockIdx.x * 256 + e] = cs;
    g_psq [blockIdx.x * 256 + e] = cq;
}

// ---------------- K6: column norm stats (reduce 128 partials per b) ------------
__global__ void k_colstats() {
    int b = blockIdx.x, e = threadIdx.x;
    float s = 0.f, sq = 0.f;
    for (int t = 0; t < 128; t++) {
        s  += g_psum[(b * 128 + t) * 256 + e];
        sq += g_psq [(b * 128 + t) * 256 + e];
    }
    float mean = s * (1.0f / 1024.0f);
    float var = (sq - 1024.0f * mean * mean) * (1.0f / 1023.0f);
    var = fmaxf(var, 0.f);
    g_cmean[b * 256 + e] = mean;
    g_crstd[b * 256 + e] = 1.0f / (sqrtf(var) + 1e-6f);
}

// ---------------- K7: GEMM  C[M,*] = A'[M,256] @ W[*,256]^T + bias -------------
// 32x64 tile, 128 threads, thread tile 4x4 f32x2. grid (128, ncols/64).
__global__ void k_gemm(const float* __restrict__ Aext, const float* __restrict__ W,
                       const float* __restrict__ bias, float* __restrict__ Cext,
                       int asel, int csel, int srcLayout, int normA) {
    __shared__ float As[32 * 66];
    __shared__ float Ws[64 * 66];
    const float* A = (asel == 0) ? g_tA : (asel == 2) ? g_o : Aext;
    int m0 = blockIdx.x * 32, i0 = blockIdx.y * 64;
    int t = threadIdx.x;
    int tr = t >> 4, ti = t & 15;
    unsigned long long acc2[4][4];
    #pragma unroll
    for (int a = 0; a < 4; a++)
        #pragma unroll
        for (int c = 0; c < 4; c++) acc2[a][c] = 0ull;

    for (int kt = 0; kt < 256; kt += 64) {
        #pragma unroll
        for (int l = 0; l < 16; l++) {
            int idx = t + l * 128;
            int r = idx >> 6, k = idx & 63;
            int bn = m0 + r;
            int abase;
            if (srcLayout) { int b = bn >> 10, n = bn & 1023; abase = (n * Bb + b) * 256; }
            else abase = bn * 256;
            float v = A[abase + kt + k];
            if (normA) {
                int b = bn >> 10;
                v = (v - g_cmean[b * 256 + kt + k]) * g_crstd[b * 256 + kt + k];
            }
            As[r * 66 + k] = v;
        }
        #pragma unroll
        for (int l = 0; l < 32; l++) {
            int idx = t + l * 128;
            int r = idx >> 6, k = idx & 63;
            Ws[r * 66 + k] = W[(i0 + r) * 256 + kt + k];
        }
        __syncthreads();
        #pragma unroll
        for (int k2 = 0; k2 < 32; k2++) {
            unsigned long long a2[4], w2[4];
            #pragma unroll
            for (int rr = 0; rr < 4; rr++)
                a2[rr] = *(const unsigned long long*)&As[(tr + rr * 8) * 66 + 2 * k2];
            #pragma unroll
            for (int ii = 0; ii < 4; ii++)
                w2[ii] = *(const unsigned long long*)&Ws[(ti + ii * 16) * 66 + 2 * k2];
            #pragma unroll
            for (int rr = 0; rr < 4; rr++)
                #pragma unroll
                for (int ii = 0; ii < 4; ii++)
                    ffma2(acc2[rr][ii], a2[rr], w2[ii]);
        }
        __syncthreads();
    }

    if (csel == 5) {
        float* C = (i0 < 256) ? g_q : g_k;
        int cbase = i0 & 255;
        #pragma unroll
        for (int rr = 0; rr < 4; rr++)
            #pragma unroll
            for (int ii = 0; ii < 4; ii++)
                C[(m0 + tr + rr * 8) * 256 + cbase + ti + ii * 16] =
                    f2sum(acc2[rr][ii]) + bias[i0 + ti + ii * 16];
    } else {
        float* C = (csel == 0) ? g_tB : (csel == 3) ? g_v : (Cext ? Cext : g_xout);
        #pragma unroll
        for (int rr = 0; rr < 4; rr++)
            #pragma unroll
            for (int ii = 0; ii < 4; ii++)
                C[(m0 + tr + rr * 8) * 256 + i0 + ti + ii * 16] =
                    f2sum(acc2[rr][ii]) + bias[i0 + ti + ii * 16];
    }
}

// ---------------- K8: MHA flash (128 threads, 4 rows/thread) -------------------
__global__ void __launch_bounds__(128, 4) k_mha_flash() {
    __shared__ float Qs[64 * 34];
    __shared__ float Ks[64 * 34];
    __shared__ float Vs[32 * 66];
    __shared__ float Ps[64 * 66];
    int tile = blockIdx.x, b = blockIdx.y, h = blockIdx.z;
    int t = threadIdx.x, tr = t >> 3, ti = t & 7;
    int q0 = tile * 64;
    const float scale = 0.17677669529663689f;

    #pragma unroll
    for (int i = 0; i < 16; i++) {
        int idx = i * 128 + t;
        int r = idx >> 5, d = idx & 31;
        Qs[r * 34 + d] = g_q[((size_t)b * Nn + q0 + r) * 256 + h * 32 + d];
    }

    float m_run[4], l_run[4];
    unsigned long long acc2[4][4];
    #pragma unroll
    for (int r = 0; r < 4; r++) {
        m_run[r] = -1e30f; l_run[r] = 0.f;
        #pragma unroll
        for (int j = 0; j < 4; j++) acc2[r][j] = 0ull;
    }
    __syncthreads();

    for (int ch = 0; ch < 16; ch++) {
        int m0 = ch * 64;
        #pragma unroll
        for (int i = 0; i < 16; i++) {
            int idx = i * 128 + t;
            int c = idx >> 5, d = idx & 31;
            Ks[c * 34 + d] = g_k[((size_t)b * Nn + m0 + c) * 256 + h * 32 + d];
            Vs[d * 66 + c] = g_v[((size_t)b * Nn + m0 + c) * 256 + h * 32 + d];
        }
        __syncthreads();

        unsigned long long sa[4][8];
        #pragma unroll
        for (int r = 0; r < 4; r++)
            #pragma unroll
            for (int c = 0; c < 8; c++) sa[r][c] = 0ull;
        #pragma unroll
        for (int d2 = 0; d2 < 16; d2++) {
            unsigned long long q2[4], k2[8];
            #pragma unroll
            for (int r = 0; r < 4; r++)
                q2[r] = *(const unsigned long long*)&Qs[(tr * 4 + r) * 34 + 2 * d2];
            #pragma unroll
            for (int c = 0; c < 8; c++)
                k2[c] = *(const unsigned long long*)&Ks[(ti * 8 + c) * 34 + 2 * d2];
            #pragma unroll
            for (int r = 0; r < 4; r++)
                #pragma unroll
                for (int c = 0; c < 8; c++)
                    ffma2(sa[r][c], q2[r], k2[c]);
        }
        #pragma unroll
        for (int r = 0; r < 4; r++) {
            float s[8];
            float cm = -1e30f;
            #pragma unroll
            for (int c = 0; c < 8; c++) {
                s[c] = f2sum(sa[r][c]) * scale;
                cm = fmaxf(cm, s[c]);
            }
            #pragma unroll
            for (int o = 1; o < 8; o <<= 1) cm = fmaxf(cm, __shfl_xor_sync(0xffffffffu, cm, o));
            float m_new = fmaxf(m_run[r], cm);
            float sc = __expf(m_run[r] - m_new);
            m_run[r] = m_new;
            unsigned long long sc2 = dup2(sc);
            #pragma unroll
            for (int j = 0; j < 4; j++) fmul2(acc2[r][j], sc2);
            float rs = 0.f;
            #pragma unroll
            for (int c = 0; c < 8; c++) {
                float p = __expf(s[c] - m_new);
                Ps[(tr * 4 + r) * 66 + ti * 8 + c] = p;
                rs += p;
            }
            #pragma unroll
            for (int o = 1; o < 8; o <<= 1) rs += __shfl_xor_sync(0xffffffffu, rs, o);
            l_run[r] = l_run[r] * sc + rs;
        }
        __syncthreads();
        #pragma unroll
        for (int k2i = 0; k2i < 32; k2i++) {
            unsigned long long a2[4], w2[4];
            #pragma unroll
            for (int r = 0; r < 4; r++)
                a2[r] = *(const unsigned long long*)&Ps[(tr * 4 + r) * 66 + 2 * k2i];
            #pragma unroll
            for (int j = 0; j < 4; j++)
                w2[j] = *(const unsigned long long*)&Vs[(ti * 4 + j) * 66 + 2 * k2i];
            #pragma unroll
            for (int r = 0; r < 4; r++)
                #pragma unroll
                for (int j = 0; j < 4; j++)
                    ffma2(acc2[r][j], a2[r], w2[j]);
        }
        __syncthreads();
    }

    #pragma unroll
    for (int r = 0; r < 4; r++) {
        int n = q0 + tr * 4 + r;
        float inv = 1.0f / l_run[r];
        #pragma unroll
        for (int j = 0; j < 4; j++)
            g_o[((size_t)b * Nn + n) * 256 + h * 32 + ti * 4 + j] =
                f2sum(acc2[r][j]) * inv;
    }
}

// ---------------- launch ----------------
extern "C" void kernel_launch(void* const* d_in, const int* in_sizes, int n_in,
                              void* d_out, int out_size) {
    const float* x          = (const float*)d_in[0];
    const float* src        = (const float*)d_in[1];
    const int*   adj        = (const int*)  d_in[2];
    const float* Wg         = (const float*)d_in[3];
    const float* a1         = (const float*)d_in[4];
    const float* a2         = (const float*)d_in[5];
    const float* lin_w      = (const float*)d_in[6];
    const float* lin_b      = (const float*)d_in[7];
    const float* in_proj_w  = (const float*)d_in[8];
    const float* in_proj_b  = (const float*)d_in[9];
    const float* out_proj_w = (const float*)d_in[10];
    const float* out_proj_b = (const float*)d_in[11];
    float* out = (float*)d_out;

    const int XSZ = Bb * Nn * Ee;
    const int ESZ = Bb * Nn * Nn;

    float* x_dst;
    float* e_dst;
    if (out_size >= XSZ + ESZ) { x_dst = out;      e_dst = out + XSZ; }
    else if (out_size == ESZ)  { x_dst = nullptr;  e_dst = out; }
    else                       { x_dst = out;      e_dst = nullptr; }

    // side streams + events (created once, on the uncaptured correctness call)
    static cudaStream_t sV = nullptr, sE = nullptr;
    static cudaEvent_t evRoot, evV, evA, evGat, evE;
    if (!sV) {
        cudaStreamCreateWithFlags(&sV, cudaStreamNonBlocking);
        cudaStreamCreateWithFlags(&sE, cudaStreamNonBlocking);
        cudaEventCreateWithFlags(&evRoot, cudaEventDisableTiming);
        cudaEventCreateWithFlags(&evV,    cudaEventDisableTiming);
        cudaEventCreateWithFlags(&evA,    cudaEventDisableTiming);
        cudaEventCreateWithFlags(&evGat,  cudaEventDisableTiming);
        cudaEventCreateWithFlags(&evE,    cudaEventDisableTiming);
    }

    cudaEventRecord(evRoot, 0);

    // fork: v-GEMM depends only on src — side stream sV
    cudaStreamWaitEvent(sV, evRoot, 0);
    k_gemm<<<dim3(128, 4), 128, 0, sV>>>(src, in_proj_w + 512 * 256, in_proj_b + 512,
                                         nullptr, 3, 3, 1, 0);
    cudaEventRecord(evV, sV);

    // fork: adjpack depends only on adj — side stream sE (overlaps k_wh2)
    cudaStreamWaitEvent(sE, evRoot, 0);
    k_adjpack<<<Bb * Nn, 256, 0, sE>>>(adj);
    cudaEventRecord(evA, sE);

    // GAT — main stream
    k_wh2<<<dim3(32, Hh), 256>>>(x, Wg, a1, a2);
    cudaStreamWaitEvent(0, evA, 0);           // adjbits ready
    k_gat_flash<<<dim3(16, Bb, Hh), 128>>>(x);

    // fork: e_out recompute is independent of the norm/GEMM/MHA chain
    cudaEventRecord(evGat, 0);
    cudaStreamWaitEvent(sE, evGat, 0);
    k_eout2<<<Bb * Nn, 256, 0, sE>>>(e_dst);
    cudaEventRecord(evE, sE);

    // norm 1 (rownorm emits col partials; colstats reduces)
    k_rownorm<<<512, 256>>>(0);
    k_colstats<<<Bb, 256>>>();

    // lin (col-norm fused into A load)
    k_gemm<<<dim3(128, 4), 128>>>(nullptr, lin_w, lin_b, nullptr, 0, 0, 0, 1);

    // norm 2
    k_rownorm<<<512, 256>>>(1);
    k_colstats<<<Bb, 256>>>();

    // fused q+k GEMM (col-norm fused into A load), W = in_proj rows [0,512)
    k_gemm<<<dim3(128, 8), 128>>>(nullptr, in_proj_w, in_proj_b, nullptr, 0, 5, 0, 1);

    // join v before MHA
    cudaStreamWaitEvent(0, evV, 0);

    // MHA flash
    k_mha_flash<<<dim3(16, Bb, Hh), 128>>>();

    // out projection
    k_gemm<<<dim3(128, 4), 128>>>(nullptr, out_proj_w, out_proj_b, x_dst, 2, 4, 0, 0);

    // join e_out before returning
    cudaStreamWaitEvent(0, evE, 0);
}

// round 17
// speedup vs baseline: 1.2264x; 1.2264x over previous
#include <cuda_runtime.h>
#include <cuda_bf16.h>
#include <math.h>

#define Bb 4
#define Nn 1024
#define Ee 256
#define Hh 8
#define Dd 32

// ---------------- scratch (device globals; referenced ONLY inside kernels) ----
__device__ float g_Wh[(size_t)Hh*Bb*Nn*Dd];        // [h][b][n][d]  4MB
__device__ float g_s1[Hh*Bb*Nn];
__device__ float g_s2[Hh*Bb*Nn];
__device__ float g_rmx[Hh*Bb*Nn];                  // GAT softmax row max
__device__ float g_rsm[Hh*Bb*Nn];                  // GAT softmax row sum
__device__ unsigned g_adjbits[Bb*Nn*32];           // packed adjacency
__device__ float g_x1[Bb*Nn*Ee];                   // GAT residual output
__device__ float g_tA[Bb*Nn*Ee];
__device__ float g_tB[Bb*Nn*Ee];
__device__ float g_q[Bb*Nn*Ee];
__device__ float g_k[Bb*Nn*Ee];
__device__ float g_v[Bb*Nn*Ee];
__device__ float g_o[Bb*Nn*Ee];
__device__ float g_eout[(size_t)Bb*Nn*Nn];         // e_out staging (only if unused output)
__device__ float g_xout[Bb*Nn*Ee];                 // x staging
__device__ float g_psum[512*Ee];                   // per-rownorm-block col partials
__device__ float g_psq [512*Ee];
__device__ float g_cmean[Bb*Ee];
__device__ float g_crstd[Bb*Ee];

// ---------------- helpers ----------------
__device__ __forceinline__ void ffma2(unsigned long long& acc,
                                      unsigned long long a, unsigned long long b) {
    asm("fma.rn.f32x2 %0, %1, %2, %0;" : "+l"(acc) : "l"(a), "l"(b));
}
__device__ __forceinline__ void fmul2(unsigned long long& acc, unsigned long long s) {
    asm("mul.rn.f32x2 %0, %0, %1;" : "+l"(acc) : "l"(s));
}
__device__ __forceinline__ unsigned long long dup2(float x) {
    unsigned long long r;
    asm("mov.b64 %0, {%1, %1};" : "=l"(r) : "f"(x));
    return r;
}
__device__ __forceinline__ float f2lo(unsigned long long p) {
    return __uint_as_float((unsigned)(p & 0xffffffffu));
}
__device__ __forceinline__ float f2hi(unsigned long long p) {
    return __uint_as_float((unsigned)(p >> 32));
}
__device__ __forceinline__ float f2sum(unsigned long long p) { return f2lo(p) + f2hi(p); }

// ---------------- K0: pack adjacency into bitmasks ----------------
__global__ void k_adjpack(const int* __restrict__ adj) {
    int row = blockIdx.x;                 // b*N + n
    int w = threadIdx.x >> 5, lane = threadIdx.x & 31;
    #pragma unroll
    for (int i = 0; i < 4; i++) {
        int u = w * 4 + i;
        unsigned bit = adj[(size_t)row * Nn + u * 32 + lane] > 0 ? 1u : 0u;
        unsigned mask = __ballot_sync(0xffffffffu, bit);
        if (lane == 0) g_adjbits[row * 32 + u] = mask;
    }
}

// ---------------- K1: Wh = x @ Wg per head, GEMM-tiled, s1/s2 fused ------------
__global__ void k_wh2(const float* __restrict__ x, const float* __restrict__ Wg,
                      const float* __restrict__ a1, const float* __restrict__ a2) {
    __shared__ float As[128 * 66];   // [row][f-chunk]  33.8KB
    __shared__ float Ws[32 * 66];    // [d][f-chunk]    8.4KB (Wg transposed)
    int tile = blockIdx.x, h = blockIdx.y;
    int t = threadIdx.x;
    int tr = t >> 4, ti = t & 15;
    int bn0 = tile * 128;
    int b = bn0 >> 10;
    int hb = h * Bb + b;

    unsigned long long acc2[8][2];
    #pragma unroll
    for (int r = 0; r < 8; r++) { acc2[r][0] = 0ull; acc2[r][1] = 0ull; }

    for (int kt = 0; kt < 256; kt += 64) {
        #pragma unroll
        for (int i = 0; i < 32; i++) {
            int idx = i * 256 + t;
            int r = idx >> 6, k = idx & 63;
            As[r * 66 + k] = x[(size_t)(bn0 + r) * 256 + kt + k];
        }
        #pragma unroll
        for (int i = 0; i < 8; i++) {
            int idx = i * 256 + t;
            int d = idx >> 6, k = idx & 63;
            Ws[d * 66 + k] = Wg[h * 8192 + (kt + k) * 32 + d];
        }
        __syncthreads();
        #pragma unroll
        for (int k2 = 0; k2 < 32; k2++) {
            unsigned long long a2[8], w2[2];
            #pragma unroll
            for (int r = 0; r < 8; r++)
                a2[r] = *(const unsigned long long*)&As[(tr + r * 16) * 66 + 2 * k2];
            w2[0] = *(const unsigned long long*)&Ws[(ti * 2 + 0) * 66 + 2 * k2];
            w2[1] = *(const unsigned long long*)&Ws[(ti * 2 + 1) * 66 + 2 * k2];
            #pragma unroll
            for (int r = 0; r < 8; r++) {
                ffma2(acc2[r][0], a2[r], w2[0]);
                ffma2(acc2[r][1], a2[r], w2[1]);
            }
        }
        __syncthreads();
    }

    float a1v0 = a1[h * 32 + ti * 2], a1v1 = a1[h * 32 + ti * 2 + 1];
    float a2v0 = a2[h * 32 + ti * 2], a2v1 = a2[h * 32 + ti * 2 + 1];
    #pragma unroll
    for (int r = 0; r < 8; r++) {
        int bn = bn0 + tr + r * 16;
        int n = bn & 1023;
        float v0 = f2sum(acc2[r][0]), v1 = f2sum(acc2[r][1]);
        *(float2*)&g_Wh[((size_t)hb * Nn + n) * 32 + ti * 2] = make_float2(v0, v1);
        float s1p = v0 * a1v0 + v1 * a1v1;
        float s2p = v0 * a2v0 + v1 * a2v1;
        #pragma unroll
        for (int o = 8; o > 0; o >>= 1) {
            s1p += __shfl_xor_sync(0xffffffffu, s1p, o);
            s2p += __shfl_xor_sync(0xffffffffu, s2p, o);
        }
        if (ti == 0) {
            g_s1[hb * Nn + n] = s1p;
            g_s2[hb * Nn + n] = s2p;
        }
    }
}

// ---------------- K2: GAT flash (128 threads, 4 rows/thread) -------------------
// Column ownership: thread ti owns cols {c*8+ti} (conflict-free Ps stores / s2 loads).
__global__ void __launch_bounds__(128, 4) k_gat_flash(const float* __restrict__ x) {
    __shared__ float Ws[32 * 66];    // [d][m]
    __shared__ float Ps[64 * 66];    // [row][m]
    __shared__ float s2s[64];
    __shared__ unsigned adjw[64 * 2];
    int tile = blockIdx.x, b = blockIdx.y, h = blockIdx.z;
    int t = threadIdx.x, tr = t >> 3, ti = t & 7;
    int n0 = tile * 64;
    int hb = h * Bb + b;
    const float* whp = g_Wh + (size_t)hb * Nn * 32;

    float s1r[4];
    #pragma unroll
    for (int r = 0; r < 4; r++) s1r[r] = g_s1[hb * Nn + n0 + tr * 4 + r];

    float m_run[4], l_run[4];
    unsigned long long acc2[4][4];
    #pragma unroll
    for (int r = 0; r < 4; r++) {
        m_run[r] = -1e30f; l_run[r] = 0.f;
        #pragma unroll
        for (int j = 0; j < 4; j++) acc2[r][j] = 0ull;
    }

    for (int ch = 0; ch < 16; ch++) {
        int m0 = ch * 64;
        #pragma unroll
        for (int i = 0; i < 16; i++) {
            int idx = i * 128 + t;
            int m = idx >> 5, d = idx & 31;
            Ws[d * 66 + m] = whp[(m0 + m) * 32 + d];
        }
        if (t < 64) s2s[t] = g_s2[hb * Nn + m0 + t];
        { int rl = t >> 1, u = t & 1;
          adjw[rl * 2 + u] = g_adjbits[(size_t)(b * Nn + n0 + rl) * 32 + (m0 >> 5) + u]; }
        __syncthreads();

        float s2v[8];
        #pragma unroll
        for (int c = 0; c < 8; c++) s2v[c] = s2s[c * 8 + ti];   // col = c*8+ti
        unsigned aw0[4], aw1[4];
        #pragma unroll
        for (int r = 0; r < 4; r++) {
            aw0[r] = adjw[(tr * 4 + r) * 2 + 0];
            aw1[r] = adjw[(tr * 4 + r) * 2 + 1];
        }

        float cmax[4];
        #pragma unroll
        for (int r = 0; r < 4; r++) {
            float cm = -1e30f;
            #pragma unroll
            for (int c = 0; c < 8; c++) {
                int ml = c * 8 + ti;
                unsigned w = (ml < 32) ? aw0[r] : aw1[r];
                float e = s1r[r] + s2v[c];
                e = e >= 0.f ? e : 0.1f * e;
                if (!((w >> (ml & 31)) & 1u)) e = -9e15f;
                cm = fmaxf(cm, e);
            }
            #pragma unroll
            for (int o = 1; o < 8; o <<= 1) cm = fmaxf(cm, __shfl_xor_sync(0xffffffffu, cm, o));
            cmax[r] = cm;
        }
        #pragma unroll
        for (int r = 0; r < 4; r++) {
            float m_new = fmaxf(m_run[r], cmax[r]);
            float sc = __expf(m_run[r] - m_new);
            m_run[r] = m_new;
            unsigned long long sc2 = dup2(sc);
            #pragma unroll
            for (int j = 0; j < 4; j++) fmul2(acc2[r][j], sc2);
            float rs = 0.f;
            #pragma unroll
            for (int c = 0; c < 8; c++) {
                int ml = c * 8 + ti;
                unsigned w = (ml < 32) ? aw0[r] : aw1[r];
                float e = s1r[r] + s2v[c];
                e = e >= 0.f ? e : 0.1f * e;
                if (!((w >> (ml & 31)) & 1u)) e = -9e15f;
                float p = __expf(e - m_new);
                Ps[(tr * 4 + r) * 66 + ml] = p;
                rs += p;
            }
            #pragma unroll
            for (int o = 1; o < 8; o <<= 1) rs += __shfl_xor_sync(0xffffffffu, rs, o);
            l_run[r] = l_run[r] * sc + rs;
        }
        __syncthreads();
        #pragma unroll
        for (int k2 = 0; k2 < 32; k2++) {
            unsigned long long a2[4], w2[4];
            #pragma unroll
            for (int r = 0; r < 4; r++)
                a2[r] = *(const unsigned long long*)&Ps[(tr * 4 + r) * 66 + 2 * k2];
            #pragma unroll
            for (int j = 0; j < 4; j++)
                w2[j] = *(const unsigned long long*)&Ws[(ti * 4 + j) * 66 + 2 * k2];
            #pragma unroll
            for (int r = 0; r < 4; r++)
                #pragma unroll
                for (int j = 0; j < 4; j++)
                    ffma2(acc2[r][j], a2[r], w2[j]);
        }
        __syncthreads();
    }

    #pragma unroll
    for (int r = 0; r < 4; r++) {
        int n = n0 + tr * 4 + r;
        float inv = 1.0f / l_run[r];
        if (ti == 0) {
            g_rmx[hb * Nn + n] = m_run[r];
            g_rsm[hb * Nn + n] = l_run[r];
        }
        #pragma unroll
        for (int j = 0; j < 4; j++) {
            float v = f2sum(acc2[r][j]) * inv;
            v = v >= 0.f ? v : 0.01f * v;
            int idx = (b * Nn + n) * 256 + h * 32 + ti * 4 + j;
            g_x1[idx] = x[idx] + v;
        }
    }
}

// ---------------- K3: e_out recompute from stats ----------------
__global__ void k_eout2(float* __restrict__ out) {
    __shared__ float s2all[8 * 1024];
    __shared__ unsigned adjw[32];
    __shared__ float mxs[8], invs[8], s1s[8];
    int n = blockIdx.x & 1023;
    int b = blockIdx.x >> 10;
    int t = threadIdx.x;
    #pragma unroll
    for (int i = 0; i < 32; i++) {
        int idx = i * 256 + t;
        s2all[idx] = g_s2[((idx >> 10) * Bb + b) * Nn + (idx & 1023)];
    }
    if (t < 32) adjw[t] = g_adjbits[(size_t)(b * Nn + n) * 32 + t];
    if (t < 8) {
        int hb = t * Bb + b;
        mxs[t]  = g_rmx[hb * Nn + n];
        invs[t] = 1.0f / g_rsm[hb * Nn + n];
        s1s[t]  = g_s1[hb * Nn + n];
    }
    __syncthreads();
    float* dst = out ? out : g_eout;
    #pragma unroll
    for (int i = 0; i < 4; i++) {
        int m = t + i * 256;
        unsigned bit = (adjw[m >> 5] >> (m & 31)) & 1u;
        float acc = 0.f;
        #pragma unroll
        for (int h = 0; h < 8; h++) {
            float e = s1s[h] + s2all[h * 1024 + m];
            e = e >= 0.f ? e : 0.1f * e;
            if (!bit) e = -9e15f;
            acc += __expf(e - mxs[h]) * invs[h];
        }
        dst[((size_t)b * Nn + n) * Nn + m] = acc * 0.125f;
    }
}

// ---------------- K5: row norm warp-per-row + fused col partials ---------------
__global__ void k_rownorm(int sel) {
    __shared__ float vs[8 * 264];   // 8 rows x 256 (+pad)
    const float* in = sel ? g_tB : g_x1;
    int w = threadIdx.x >> 5, lane = threadIdx.x & 31;
    int bn = blockIdx.x * 8 + w;
    const float* p = in + (size_t)bn * 256 + lane * 8;
    float4 v0 = *(const float4*)p;
    float4 v1 = *(const float4*)(p + 4);
    float s = v0.x + v0.y + v0.z + v0.w + v1.x + v1.y + v1.z + v1.w;
    #pragma unroll
    for (int o = 16; o > 0; o >>= 1) s += __shfl_xor_sync(0xffffffffu, s, o);
    float mean = s * (1.0f / 256.0f);
    float d0 = v0.x-mean, d1 = v0.y-mean, d2 = v0.z-mean, d3 = v0.w-mean;
    float d4 = v1.x-mean, d5 = v1.y-mean, d6 = v1.z-mean, d7 = v1.w-mean;
    float q = d0*d0+d1*d1+d2*d2+d3*d3+d4*d4+d5*d5+d6*d6+d7*d7;
    #pragma unroll
    for (int o = 16; o > 0; o >>= 1) q += __shfl_xor_sync(0xffffffffu, q, o);
    float inv = 1.0f / (sqrtf(q * (1.0f / 255.0f)) + 1e-6f);
    float r0 = d0*inv, r1 = d1*inv, r2 = d2*inv, r3 = d3*inv;
    float r4 = d4*inv, r5 = d5*inv, r6 = d6*inv, r7 = d7*inv;
    float* op = g_tA + (size_t)bn * 256 + lane * 8;
    *(float4*)op       = make_float4(r0, r1, r2, r3);
    *(float4*)(op + 4) = make_float4(r4, r5, r6, r7);
    int cb = w * 264 + lane * 8;
    vs[cb+0]=r0; vs[cb+1]=r1; vs[cb+2]=r2; vs[cb+3]=r3;
    vs[cb+4]=r4; vs[cb+5]=r5; vs[cb+6]=r6; vs[cb+7]=r7;
    __syncthreads();
    int e = threadIdx.x;
    float cs = 0.f, cq = 0.f;
    #pragma unroll
    for (int r = 0; r < 8; r++) {
        float v = vs[r * 264 + e];
        cs += v; cq += v * v;
    }
    g_psum[blockIdx.x * 256 + e] = cs;
    g_psq [blockIdx.x * 256 + e] = cq;
}

// ---------------- K6: column norm stats (reduce 128 partials per b) ------------
__global__ void k_colstats() {
    int b = blockIdx.x, e = threadIdx.x;
    float s = 0.f, sq = 0.f;
    for (int t = 0; t < 128; t++) {
        s  += g_psum[(b * 128 + t) * 256 + e];
        sq += g_psq [(b * 128 + t) * 256 + e];
    }
    float mean = s * (1.0f / 1024.0f);
    float var = (sq - 1024.0f * mean * mean) * (1.0f / 1023.0f);
    var = fmaxf(var, 0.f);
    g_cmean[b * 256 + e] = mean;
    g_crstd[b * 256 + e] = 1.0f / (sqrtf(var) + 1e-6f);
}

// ---------------- K7: GEMM  C[M,*] = A'[M,256] @ W[*,256]^T + bias -------------
__global__ void k_gemm(const float* __restrict__ Aext, const float* __restrict__ W,
                       const float* __restrict__ bias, float* __restrict__ Cext,
                       int asel, int csel, int srcLayout, int normA) {
    __shared__ float As[32 * 66];
    __shared__ float Ws[64 * 66];
    const float* A = (asel == 0) ? g_tA : (asel == 2) ? g_o : Aext;
    int m0 = blockIdx.x * 32, i0 = blockIdx.y * 64;
    int t = threadIdx.x;
    int tr = t >> 4, ti = t & 15;
    unsigned long long acc2[4][4];
    #pragma unroll
    for (int a = 0; a < 4; a++)
        #pragma unroll
        for (int c = 0; c < 4; c++) acc2[a][c] = 0ull;

    for (int kt = 0; kt < 256; kt += 64) {
        #pragma unroll
        for (int l = 0; l < 16; l++) {
            int idx = t + l * 128;
            int r = idx >> 6, k = idx & 63;
            int bn = m0 + r;
            int abase;
            if (srcLayout) { int b = bn >> 10, n = bn & 1023; abase = (n * Bb + b) * 256; }
            else abase = bn * 256;
            float v = A[abase + kt + k];
            if (normA) {
                int b = bn >> 10;
                v = (v - g_cmean[b * 256 + kt + k]) * g_crstd[b * 256 + kt + k];
            }
            As[r * 66 + k] = v;
        }
        #pragma unroll
        for (int l = 0; l < 32; l++) {
            int idx = t + l * 128;
            int r = idx >> 6, k = idx & 63;
            Ws[r * 66 + k] = W[(i0 + r) * 256 + kt + k];
        }
        __syncthreads();
        #pragma unroll
        for (int k2 = 0; k2 < 32; k2++) {
            unsigned long long a2[4], w2[4];
            #pragma unroll
            for (int rr = 0; rr < 4; rr++)
                a2[rr] = *(const unsigned long long*)&As[(tr + rr * 8) * 66 + 2 * k2];
            #pragma unroll
            for (int ii = 0; ii < 4; ii++)
                w2[ii] = *(const unsigned long long*)&Ws[(ti + ii * 16) * 66 + 2 * k2];
            #pragma unroll
            for (int rr = 0; rr < 4; rr++)
                #pragma unroll
                for (int ii = 0; ii < 4; ii++)
                    ffma2(acc2[rr][ii], a2[rr], w2[ii]);
        }
        __syncthreads();
    }

    if (csel == 5) {
        float* C = (i0 < 256) ? g_q : g_k;
        int cbase = i0 & 255;
        #pragma unroll
        for (int rr = 0; rr < 4; rr++)
            #pragma unroll
            for (int ii = 0; ii < 4; ii++)
                C[(m0 + tr + rr * 8) * 256 + cbase + ti + ii * 16] =
                    f2sum(acc2[rr][ii]) + bias[i0 + ti + ii * 16];
    } else {
        float* C = (csel == 0) ? g_tB : (csel == 3) ? g_v : (Cext ? Cext : g_xout);
        #pragma unroll
        for (int rr = 0; rr < 4; rr++)
            #pragma unroll
            for (int ii = 0; ii < 4; ii++)
                C[(m0 + tr + rr * 8) * 256 + i0 + ti + ii * 16] =
                    f2sum(acc2[rr][ii]) + bias[i0 + ti + ii * 16];
    }
}

// ---------------- K8: MHA flash (128 threads, 4 rows/thread) -------------------
// Column ownership: thread ti owns cols {c*8+ti} (conflict-free Ks loads + Ps stores).
__global__ void __launch_bounds__(128, 4) k_mha_flash() {
    __shared__ float Qs[64 * 34];
    __shared__ float Ks[64 * 34];
    __shared__ float Vs[32 * 66];
    __shared__ float Ps[64 * 66];
    int tile = blockIdx.x, b = blockIdx.y, h = blockIdx.z;
    int t = threadIdx.x, tr = t >> 3, ti = t & 7;
    int q0 = tile * 64;
    const float scale = 0.17677669529663689f;

    #pragma unroll
    for (int i = 0; i < 16; i++) {
        int idx = i * 128 + t;
        int r = idx >> 5, d = idx & 31;
        Qs[r * 34 + d] = g_q[((size_t)b * Nn + q0 + r) * 256 + h * 32 + d];
    }

    float m_run[4], l_run[4];
    unsigned long long acc2[4][4];
    #pragma unroll
    for (int r = 0; r < 4; r++) {
        m_run[r] = -1e30f; l_run[r] = 0.f;
        #pragma unroll
        for (int j = 0; j < 4; j++) acc2[r][j] = 0ull;
    }
    __syncthreads();

    for (int ch = 0; ch < 16; ch++) {
        int m0 = ch * 64;
        #pragma unroll
        for (int i = 0; i < 16; i++) {
            int idx = i * 128 + t;
            int c = idx >> 5, d = idx & 31;
            Ks[c * 34 + d] = g_k[((size_t)b * Nn + m0 + c) * 256 + h * 32 + d];
            Vs[d * 66 + c] = g_v[((size_t)b * Nn + m0 + c) * 256 + h * 32 + d];
        }
        __syncthreads();

        unsigned long long sa[4][8];
        #pragma unroll
        for (int r = 0; r < 4; r++)
            #pragma unroll
            for (int c = 0; c < 8; c++) sa[r][c] = 0ull;
        #pragma unroll
        for (int d2 = 0; d2 < 16; d2++) {
            unsigned long long q2[4], k2[8];
            #pragma unroll
            for (int r = 0; r < 4; r++)
                q2[r] = *(const unsigned long long*)&Qs[(tr * 4 + r) * 34 + 2 * d2];
            #pragma unroll
            for (int c = 0; c < 8; c++)
                k2[c] = *(const unsigned long long*)&Ks[(c * 8 + ti) * 34 + 2 * d2];
            #pragma unroll
            for (int r = 0; r < 4; r++)
                #pragma unroll
                for (int c = 0; c < 8; c++)
                    ffma2(sa[r][c], q2[r], k2[c]);
        }
        #pragma unroll
        for (int r = 0; r < 4; r++) {
            float s[8];
            float cm = -1e30f;
            #pragma unroll
            for (int c = 0; c < 8; c++) {
                s[c] = f2sum(sa[r][c]) * scale;
                cm = fmaxf(cm, s[c]);
            }
            #pragma unroll
            for (int o = 1; o < 8; o <<= 1) cm = fmaxf(cm, __shfl_xor_sync(0xffffffffu, cm, o));
            float m_new = fmaxf(m_run[r], cm);
            float sc = __expf(m_run[r] - m_new);
            m_run[r] = m_new;
            unsigned long long sc2 = dup2(sc);
            #pragma unroll
            for (int j = 0; j < 4; j++) fmul2(acc2[r][j], sc2);
            float rs = 0.f;
            #pragma unroll
            for (int c = 0; c < 8; c++) {
                float p = __expf(s[c] - m_new);
                Ps[(tr * 4 + r) * 66 + c * 8 + ti] = p;
                rs += p;
            }
            #pragma unroll
            for (int o = 1; o < 8; o <<= 1) rs += __shfl_xor_sync(0xffffffffu, rs, o);
            l_run[r] = l_run[r] * sc + rs;
        }
        __syncthreads();
        #pragma unroll
        for (int k2i = 0; k2i < 32; k2i++) {
            unsigned long long a2[4], w2[4];
            #pragma unroll
            for (int r = 0; r < 4; r++)
                a2[r] = *(const unsigned long long*)&Ps[(tr * 4 + r) * 66 + 2 * k2i];
            #pragma unroll
            for (int j = 0; j < 4; j++)
                w2[j] = *(const unsigned long long*)&Vs[(ti * 4 + j) * 66 + 2 * k2i];
            #pragma unroll
            for (int r = 0; r < 4; r++)
                #pragma unroll
                for (int j = 0; j < 4; j++)
                    ffma2(acc2[r][j], a2[r], w2[j]);
        }
        __syncthreads();
    }

    #pragma unroll
    for (int r = 0; r < 4; r++) {
        int n = q0 + tr * 4 + r;
        float inv = 1.0f / l_run[r];
        #pragma unroll
        for (int j = 0; j < 4; j++)
            g_o[((size_t)b * Nn + n) * 256 + h * 32 + ti * 4 + j] =
                f2sum(acc2[r][j]) * inv;
    }
}

// ---------------- launch ----------------
extern "C" void kernel_launch(void* const* d_in, const int* in_sizes, int n_in,
                              void* d_out, int out_size) {
    const float* x          = (const float*)d_in[0];
    const float* src        = (const float*)d_in[1];
    const int*   adj        = (const int*)  d_in[2];
    const float* Wg         = (const float*)d_in[3];
    const float* a1         = (const float*)d_in[4];
    const float* a2         = (const float*)d_in[5];
    const float* lin_w      = (const float*)d_in[6];
    const float* lin_b      = (const float*)d_in[7];
    const float* in_proj_w  = (const float*)d_in[8];
    const float* in_proj_b  = (const float*)d_in[9];
    const float* out_proj_w = (const float*)d_in[10];
    const float* out_proj_b = (const float*)d_in[11];
    float* out = (float*)d_out;

    const int XSZ = Bb * Nn * Ee;
    const int ESZ = Bb * Nn * Nn;

    float* x_dst;
    float* e_dst;
    if (out_size >= XSZ + ESZ) { x_dst = out;      e_dst = out + XSZ; }
    else if (out_size == ESZ)  { x_dst = nullptr;  e_dst = out; }
    else                       { x_dst = out;      e_dst = nullptr; }

    static cudaStream_t sV = nullptr, sE = nullptr;
    static cudaEvent_t evRoot, evV, evA, evGat, evE;
    if (!sV) {
        cudaStreamCreateWithFlags(&sV, cudaStreamNonBlocking);
        cudaStreamCreateWithFlags(&sE, cudaStreamNonBlocking);
        cudaEventCreateWithFlags(&evRoot, cudaEventDisableTiming);
        cudaEventCreateWithFlags(&evV,    cudaEventDisableTiming);
        cudaEventCreateWithFlags(&evA,    cudaEventDisableTiming);
        cudaEventCreateWithFlags(&evGat,  cudaEventDisableTiming);
        cudaEventCreateWithFlags(&evE,    cudaEventDisableTiming);
    }

    cudaEventRecord(evRoot, 0);

    // fork: v-GEMM depends only on src
    cudaStreamWaitEvent(sV, evRoot, 0);
    k_gemm<<<dim3(128, 4), 128, 0, sV>>>(src, in_proj_w + 512 * 256, in_proj_b + 512,
                                         nullptr, 3, 3, 1, 0);
    cudaEventRecord(evV, sV);

    // fork: adjpack depends only on adj
    cudaStreamWaitEvent(sE, evRoot, 0);
    k_adjpack<<<Bb * Nn, 256, 0, sE>>>(adj);
    cudaEventRecord(evA, sE);

    // GAT — main stream
    k_wh2<<<dim3(32, Hh), 256>>>(x, Wg, a1, a2);
    cudaStreamWaitEvent(0, evA, 0);
    k_gat_flash<<<dim3(16, Bb, Hh), 128>>>(x);

    // fork: e_out recompute
    cudaEventRecord(evGat, 0);
    cudaStreamWaitEvent(sE, evGat, 0);
    k_eout2<<<Bb * Nn, 256, 0, sE>>>(e_dst);
    cudaEventRecord(evE, sE);

    // norm 1
    k_rownorm<<<512, 256>>>(0);
    k_colstats<<<Bb, 256>>>();

    // lin
    k_gemm<<<dim3(128, 4), 128>>>(nullptr, lin_w, lin_b, nullptr, 0, 0, 0, 1);

    // norm 2
    k_rownorm<<<512, 256>>>(1);
    k_colstats<<<Bb, 256>>>();

    // fused q+k GEMM
    k_gemm<<<dim3(128, 8), 128>>>(nullptr, in_proj_w, in_proj_b, nullptr, 0, 5, 0, 1);

    // join v before MHA
    cudaStreamWaitEvent(0, evV, 0);

    // MHA flash
    k_mha_flash<<<dim3(16, Bb, Hh), 128>>>();

    // out projection
    k_gemm<<<dim3(128, 4), 128>>>(nullptr, out_proj_w, out_proj_b, x_dst, 2, 4, 0, 0);

    // join e_out
    cudaStreamWaitEvent(0, evE, 0);
}